// round 17
// baseline (speedup 1.0000x reference)
#include <cuda_runtime.h>
#include <cstdint>

// Problem constants (from reference)
#define SEQ    4096
#define CIN    7
#define NK     586        // 585 regular kernels + 1 "last"
#define GLEN   12288      // SEQ * KW(3)
#define HP     12289      // output positions per channel-kernel row
#define CTOT   4096       // 7*585 + 1
#define NQ     1024       // c-quads
#define RPB    36         // rows per y-block (12 per phase)
#define NYB    342        // y-blocks (342*36 = 12312 >= HP)
#define LASTBY 341

typedef unsigned long long u64;

// Scratch (allocation-free rule: __device__ globals)
__device__ float g_Wmid[NK * 8];        // raw mid-column weights (slow/edge path)
__device__ ulonglong2 g_WfT[12 * NQ];   // folded weights: [(r*4+m)*NQ + quad] -> {(f_c0,f_c1),(f_c2,f_c3)}

__device__ __forceinline__ u64 pk2(float lo, float hi) {
    u64 r; asm("mov.b64 %0, {%1,%2};" : "=l"(r) : "f"(lo), "f"(hi)); return r;
}
__device__ __forceinline__ u64 fma2(u64 a, u64 b, u64 c) {
    u64 d; asm("fma.rn.f32x2 %0, %1, %2, %3;" : "=l"(d) : "l"(a), "l"(b), "l"(c)); return d;
}

// g_ch[t]: gathered signal with clamping; 0 outside [0, GLEN)
__device__ __forceinline__ float gatherg(const float* __restrict__ x, int ch, int t) {
    if (t < 0 || t >= GLEN) return 0.f;
    int s = t / 3;
    int j = t - s * 3;
    int src = s + j;
    if (src > SEQ - 1) src = SEQ - 1;
    return x[src * CIN + ch];
}

// ---- prep: raw mid-column weights + phase-folded 4-tap weights ----
__global__ void prep(const float* __restrict__ kernels) {
    int idx = blockIdx.x * blockDim.x + threadIdx.x;
    if (idx < NK * 8) {
        int k = idx >> 3, a = idx & 7;
        g_Wmid[idx] = kernels[k * 24 + a * 3 + 1];
    }
    if (idx < 12 * NQ) {
        int rm = idx / NQ, quad = idx - rm * NQ;
        int r = rm >> 2, m = rm & 3;
        float f[4];
#pragma unroll
        for (int j = 0; j < 4; j++) {
            int c  = quad * 4 + j;
            int kk = (c == CTOT - 1) ? 585 : (c % 585);
            const float* wk = &kernels[kk * 24];
            float w[8];
#pragma unroll
            for (int a = 0; a < 8; a++) w[a] = wk[a * 3 + 1];
            float v;
            if (r == 0)
                v = (m == 0) ? w[0] : (m == 1) ? (w[1] + w[3])
                  : (m == 2) ? (w[2] + w[4] + w[6]) : (w[5] + w[7]);
            else if (r == 1)
                v = (m == 0) ? (w[0] + w[2]) : (m == 1) ? (w[1] + w[3] + w[5])
                  : (m == 2) ? (w[4] + w[6]) : w[7];
            else
                v = (m == 0) ? w[1] : (m == 1) ? (w[0] + w[2] + w[4])
                  : (m == 2) ? (w[3] + w[5] + w[7]) : w[6];
            f[j] = v;
        }
        ulonglong2 t; t.x = pk2(f[0], f[1]); t.y = pk2(f[2], f[3]);
        g_WfT[idx] = t;
    }
}

// One row of the fast path: literal k -> ring indices and STG byte-offset are
// compile-time; one STG.128 stores 4 outputs.
#define ROWQ(k) do {                                                           \
    u64 a0 = 0ull, a1 = 0ull;                                                  \
    _Pragma("unroll")                                                          \
    for (int m = 0; m < 4; m++) {                                              \
        a0 = fma2(P[(k) + m], W0[m], a0);                                      \
        a1 = fma2(P[(k) + m], W1[m], a1);                                      \
    }                                                                          \
    asm volatile("st.global.cs.v2.u64 [%0+%1], {%2,%3};"                       \
                 :: "l"(op), "n"((k) * 3 * CTOT * (int)sizeof(float)),         \
                    "l"(a0), "l"(a1) : "memory");                              \
} while (0)

// ---- main kernel: phase-folded 4-tap conv, one c-quad per thread,
//      12 rows (one phase of a 36-row block), STG.128 per row ----
__global__ void __launch_bounds__(256, 4) conv_main(const float* __restrict__ x,
                                                    float* __restrict__ out) {
    const int tid = threadIdx.x;
    const int bx  = blockIdx.x;                 // [0, 4)
    const int byp = blockIdx.y;                 // [0, 3*NYB)
    const int by  = byp / 3;
    const int p   = byp - 3 * by;               // phase offset within row-block
    const int quad = bx * 256 + tid;            // [0, 1024)
    const int c0   = quad * 4;
    const int H0   = by * RPB;

    // Phase parameters: rows h = H0 + 3k + p, r = (h-4) mod 3 (uniform), q = q0 + k
    const int e0 = H0 + p - 4;
    const int r  = ((e0 % 3) + 3) % 3;
    const int q0 = (e0 - r) / 3;
    const int mb = (r == 0) ? 0 : 1;
    const int qb = q0 + mb;

    // Channels spanned by this CTA's 1024 c-columns (up to 3)
    const int chLo = (bx * 1024) / 585;

    __shared__ __align__(16) u64 win[3][16];    // dup (x,x) pairs, Xd[qb+i] per channel

    if (tid < 48) {
        int w  = tid >> 4, i = tid & 15;
        int ch = min(chLo + w, CIN - 1);
        int iq = qb + i;
        float v = (iq < 0) ? 0.f : x[min(iq, SEQ - 1) * CIN + ch];
        win[w][i] = pk2(v, v);
    }
    __syncthreads();

    const int ch0 = c0 / 585;
    const int c3v = c0 + 3;
    const int ch3 = (c3v == CTOT - 1) ? 0 : c3v / 585;
    const bool uniform = (ch0 == ch3);

    if (uniform && by != 0 && by != LASTBY) {
        // Fast path: all 12 rows interior (4 <= h <= 12284 guaranteed).
        u64 W0[4], W1[4];
#pragma unroll
        for (int m = 0; m < 4; m++) {
            ulonglong2 t = g_WfT[(r * 4 + m) * NQ + quad];   // SoA, warp-contiguous
            W0[m] = t.x; W1[m] = t.y;
        }
        const u64* gp = &win[ch0 - chLo][0];
        u64 P[16];
#pragma unroll
        for (int i = 0; i < 8; i++) {
            ulonglong2 t = *(const ulonglong2*)(gp + 2 * i);
            P[2 * i] = t.x; P[2 * i + 1] = t.y;
        }
        char* op = (char*)(out + (size_t)(H0 + p) * CTOT + c0);
        ROWQ(0); ROWQ(1); ROWQ(2);  ROWQ(3);
        ROWQ(4); ROWQ(5); ROWQ(6);  ROWQ(7);
        ROWQ(8); ROWQ(9); ROWQ(10); ROWQ(11);
    } else {
        // General path: first/last row-blocks (edge rows) and channel-crossing quads.
        u64 W0[4], W1[4];
        if (uniform) {
#pragma unroll
            for (int m = 0; m < 4; m++) {
                ulonglong2 t = g_WfT[(r * 4 + m) * NQ + quad];
                W0[m] = t.x; W1[m] = t.y;
            }
        }
        int wi = ch0 - chLo; wi = (wi < 0) ? 0 : (wi > 2 ? 2 : wi);
        const u64* gp = &win[wi][0];
        for (int k = 0; k < 12; k++) {
            int h = H0 + 3 * k + p;
            if (h >= HP) break;
            if (uniform && h >= 4 && h <= 12284) {
                u64 a0 = 0ull, a1 = 0ull;
#pragma unroll
                for (int m = 0; m < 4; m++) {
                    a0 = fma2(gp[k + m], W0[m], a0);
                    a1 = fma2(gp[k + m], W1[m], a1);
                }
                ulonglong2 st; st.x = a0; st.y = a1;
                *(ulonglong2*)&out[(size_t)h * CTOT + c0] = st;
            } else {
                // Exact 8-tap gather (edge rows / crossing quads)
                float o[4];
#pragma unroll
                for (int j = 0; j < 4; j++) {
                    int c  = c0 + j;
                    int cc = (c == CTOT - 1) ? 0 : c / 585;
                    int kk = (c == CTOT - 1) ? 585 : c % 585;
                    float s = 0.f;
#pragma unroll
                    for (int a = 0; a < 8; a++)
                        s = fmaf(gatherg(x, cc, h - 4 + a), g_Wmid[kk * 8 + a], s);
                    o[j] = s;
                }
                float4 v; v.x = o[0]; v.y = o[1]; v.z = o[2]; v.w = o[3];
                *(float4*)&out[(size_t)h * CTOT + c0] = v;
            }
        }
    }
}

extern "C" void kernel_launch(void* const* d_in, const int* in_sizes, int n_in,
                              void* d_out, int out_size) {
    const float* x       = (const float*)d_in[0];
    const float* kernels = (const float*)d_in[1];
    if (n_in >= 2 && in_sizes[0] == NK * 24) {   // defensive: swapped order
        kernels = (const float*)d_in[0];
        x       = (const float*)d_in[1];
    }
    float* out = (float*)d_out;

    prep<<<48, 256>>>(kernels);                  // covers 12*NQ = 12288

    dim3 grid(4, 3 * NYB);                       // (4, 1026) = 4104 CTAs
    conv_main<<<grid, 256>>>(x, out);
}